// round 7
// baseline (speedup 1.0000x reference)
#include <cuda_runtime.h>
#include <math.h>
#include <stdint.h>

// Problem constants
#define B_   8
#define S_   8192
#define D_   1024
#define H_   16
#define GS_  16
#define K_   64
#define HD_  64
#define G_   512            // S/GS groups per batch
#define F_   256            // DH4 scorer hidden
#define BG_  (B_*G_)        // 4096
#define BK_  (B_*K_)        // 512

// ---------------- scratch (static __device__, no allocation) ----------------
__device__ float g_groups[BG_*D_];
__device__ float g_h[BG_*F_];
__device__ float g_scores[BG_];
__device__ int   g_topidx[BK_];
__device__ int   g_selmap[BG_];
__device__ float g_q[BK_*D_];
__device__ float g_k[BK_*D_];
__device__ float g_v[BK_*D_];
__device__ float g_ctx[BK_*D_];
__device__ float g_outg[BK_*D_];

// ---------------- 1. group mean pool ----------------
__global__ void pool_kernel(const float* __restrict__ hs) {
    int bg = blockIdx.x;
    int b = bg >> 9, g = bg & 511;
    const float* base = hs + (b*S_ + g*GS_) * D_;
    int d4 = threadIdx.x * 4;
    float4 acc = make_float4(0.f, 0.f, 0.f, 0.f);
#pragma unroll
    for (int r = 0; r < GS_; r++) {
        float4 v = *(const float4*)(base + r*D_ + d4);
        acc.x += v.x; acc.y += v.y; acc.z += v.z; acc.w += v.w;
    }
    const float inv = 1.0f / (float)GS_;
    acc.x *= inv; acc.y *= inv; acc.z *= inv; acc.w *= inv;
    *(float4*)(g_groups + bg*D_ + d4) = acc;
}

// ---------------- tf32 helpers ----------------
__device__ __forceinline__ float2 split2_tf32(float x) {
    uint32_t h;
    asm("cvt.rna.tf32.f32 %0, %1;" : "=r"(h) : "f"(x));
    float hi = __uint_as_float(h);
    float r = x - hi;
    uint32_t l;
    asm("cvt.rna.tf32.f32 %0, %1;" : "=r"(l) : "f"(r));
    return make_float2(hi, __uint_as_float(l));
}

__device__ __forceinline__ void mma_tf32(float acc[4],
                                         float a0, float a1, float a2, float a3,
                                         float b0, float b1) {
    uint32_t ua0 = __float_as_uint(a0), ua1 = __float_as_uint(a1);
    uint32_t ua2 = __float_as_uint(a2), ua3 = __float_as_uint(a3);
    uint32_t ub0 = __float_as_uint(b0), ub1 = __float_as_uint(b1);
    asm volatile(
        "mma.sync.aligned.m16n8k8.row.col.f32.tf32.tf32.f32 "
        "{%0,%1,%2,%3}, {%4,%5,%6,%7}, {%8,%9}, {%0,%1,%2,%3};\n"
        : "+f"(acc[0]), "+f"(acc[1]), "+f"(acc[2]), "+f"(acc[3])
        : "r"(ua0), "r"(ua1), "r"(ua2), "r"(ua3), "r"(ub0), "r"(ub1));
}

// ---------------- tensor-core GEMM: C = A[M,K] @ B[K,N], 3xTF32 ----------------
// 128 threads (4 warps, 2x2), block tile 64x128, K-chunk 16, warp tile 32x64.
// hi/lo interleaved as float2 in smem -> one LDS.64 per fragment element pair.
// Register prefetch pipeline overlaps global loads with the mma section.
// USE_ROWMAP: A row r reads g_groups[(r>>6)*G_ + g_topidx[r]] (fused gather).
#define KC_ 16
#define AST_ 68     // A plane stride (float2): bank-safe (8k + 2m pattern)
#define BST_ 132    // B plane stride (float2)

template<bool USE_ROWMAP>
__global__ void gemm_tf32_3x(const float* __restrict__ A,
                             const float* __restrict__ B0,
                             const float* __restrict__ B1,
                             const float* __restrict__ B2,
                             float* __restrict__ C0,
                             float* __restrict__ C1,
                             float* __restrict__ C2,
                             int M, int N, int Kd) {
    const float* Bm = (blockIdx.z == 0) ? B0 : ((blockIdx.z == 1) ? B1 : B2);
    float* C       = (blockIdx.z == 0) ? C0 : ((blockIdx.z == 1) ? C1 : C2);

    __shared__ float2 Apl[KC_][AST_];   // [k][m] (hi,lo)
    __shared__ float2 Bpl[KC_][BST_];   // [k][n] (hi,lo)

    int tid = threadIdx.x;
    int lane = tid & 31, wid = tid >> 5;
    int wm = wid & 1, wn = wid >> 1;          // 2x2 warps
    int g = lane >> 2, tig = lane & 3;

    int m0 = blockIdx.y * 64, n0 = blockIdx.x * 128;

    // A loader: row arow (0..63), k-base kb in {0,8}; 2 float4 per chunk
    int arow = tid >> 1;
    int kb = (tid & 1) << 3;
    int agrow = m0 + arow;
    if (USE_ROWMAP) agrow = ((agrow >> 6) << 9) + g_topidx[agrow];
    const float* Arow = A + (size_t)agrow * Kd + kb;

    // B loader: each warp owns rows wid, wid+4, wid+8, wid+12; permuted cols
    // bcol covers 0..127 across the warp (coalesced union, conflict-spread)
    int brow = wid;
    int bcol = ((lane >> 2) << 2) + ((lane & 3) << 5);
    const float* Bbase = Bm + (size_t)brow * N + n0 + bcol;

    float acc[2][8][4];
#pragma unroll
    for (int sm = 0; sm < 2; sm++)
#pragma unroll
        for (int sn = 0; sn < 8; sn++)
#pragma unroll
            for (int i = 0; i < 4; i++) acc[sm][sn][i] = 0.f;

    // prologue: prefetch chunk 0
    float4 pa[2], pb[4];
    pa[0] = *(const float4*)(Arow);
    pa[1] = *(const float4*)(Arow + 4);
#pragma unroll
    for (int i = 0; i < 4; i++)
        pb[i] = *(const float4*)(Bbase + (size_t)(i*4) * N);

    int aer = (lane & 1) << 1;   // A store rotation (break pair conflicts)
    int ber = lane & 3;          // B store rotation (break quad conflicts)

    for (int k0 = 0; k0 < Kd; k0 += KC_) {
        // ---- split + store prefetched tiles ----
#pragma unroll
        for (int q = 0; q < 2; q++) {
            float va[4] = {pa[q].x, pa[q].y, pa[q].z, pa[q].w};
#pragma unroll
            for (int j = 0; j < 4; j++) {
                int e = (j + aer) & 3;
                Apl[kb + q*4 + e][arow] = split2_tf32(va[e]);
            }
        }
#pragma unroll
        for (int i = 0; i < 4; i++) {
            float vb[4] = {pb[i].x, pb[i].y, pb[i].z, pb[i].w};
#pragma unroll
            for (int j = 0; j < 4; j++) {
                int e = (j + ber) & 3;
                Bpl[brow + 4*i][bcol + e] = split2_tf32(vb[e]);
            }
        }
        __syncthreads();

        // ---- prefetch next chunk (overlaps with mma below) ----
        if (k0 + KC_ < Kd) {
            pa[0] = *(const float4*)(Arow + k0 + KC_);
            pa[1] = *(const float4*)(Arow + k0 + KC_ + 4);
#pragma unroll
            for (int i = 0; i < 4; i++)
                pb[i] = *(const float4*)(Bbase + (size_t)(k0 + KC_ + i*4) * N);
        }

        // ---- mma over the chunk ----
#pragma unroll
        for (int k8 = 0; k8 < KC_; k8 += 8) {
            int ka = k8 + tig;
            float2 ap[2][4];
#pragma unroll
            for (int sm = 0; sm < 2; sm++) {
                int mb = wm*32 + sm*16;
                ap[sm][0] = Apl[ka    ][mb + g    ];
                ap[sm][1] = Apl[ka    ][mb + g + 8];
                ap[sm][2] = Apl[ka + 4][mb + g    ];
                ap[sm][3] = Apl[ka + 4][mb + g + 8];
            }
            float2 bp[8][2];
#pragma unroll
            for (int sn = 0; sn < 8; sn++) {
                int nb = wn*64 + sn*8 + g;
                bp[sn][0] = Bpl[ka    ][nb];
                bp[sn][1] = Bpl[ka + 4][nb];
            }
#pragma unroll
            for (int sm = 0; sm < 2; sm++)
#pragma unroll
                for (int sn = 0; sn < 8; sn++) {
                    mma_tf32(acc[sm][sn],
                             ap[sm][0].y, ap[sm][1].y, ap[sm][2].y, ap[sm][3].y,
                             bp[sn][0].x, bp[sn][1].x);                 // lo*hi
                    mma_tf32(acc[sm][sn],
                             ap[sm][0].x, ap[sm][1].x, ap[sm][2].x, ap[sm][3].x,
                             bp[sn][0].y, bp[sn][1].y);                 // hi*lo
                    mma_tf32(acc[sm][sn],
                             ap[sm][0].x, ap[sm][1].x, ap[sm][2].x, ap[sm][3].x,
                             bp[sn][0].x, bp[sn][1].x);                 // hi*hi
                }
        }
        __syncthreads();
    }

#pragma unroll
    for (int sm = 0; sm < 2; sm++)
#pragma unroll
        for (int sn = 0; sn < 8; sn++) {
            int row = m0 + wm*32 + sm*16 + g;
            int col = n0 + wn*64 + sn*8 + tig*2;
            *(float2*)(C + (size_t)row*N + col)     = make_float2(acc[sm][sn][0], acc[sm][sn][1]);
            *(float2*)(C + (size_t)(row+8)*N + col) = make_float2(acc[sm][sn][2], acc[sm][sn][3]);
        }
}

// ---------------- 2b. scorer epilogue: bias -> relu -> dot Ws2 ----------------
__global__ void score_reduce(const float* __restrict__ bs1,
                             const float* __restrict__ Ws2,
                             const float* __restrict__ bs2) {
    int g = blockIdx.x * 8 + (threadIdx.x >> 5);
    int lane = threadIdx.x & 31;
    float s = 0.f;
#pragma unroll
    for (int i = 0; i < 8; i++) {
        int f = lane + i*32;
        float v = g_h[g*F_ + f] + bs1[f];
        s += fmaxf(v, 0.f) * Ws2[f];
    }
#pragma unroll
    for (int o = 16; o; o >>= 1) s += __shfl_xor_sync(0xffffffffu, s, o);
    if (lane == 0) g_scores[g] = s + bs2[0];
}

// ---------------- 3. top-64 via bitonic sort (desc by score, asc by idx) -----
__global__ void topk_bitonic() {
    int b = blockIdx.x;
    int t = threadIdx.x;    // 512
    __shared__ float sv[512];
    __shared__ int   si[512];
    sv[t] = g_scores[b*G_ + t];
    si[t] = t;
    __syncthreads();
    for (int k = 2; k <= 512; k <<= 1) {
        for (int j = k >> 1; j > 0; j >>= 1) {
            int ixj = t ^ j;
            if (ixj > t) {
                float v1 = sv[t], v2 = sv[ixj];
                int   i1 = si[t], i2 = si[ixj];
                bool lt12 = (v1 < v2) || (v1 == v2 && i1 > i2);
                bool swap = ((t & k) == 0) ? lt12 : !lt12;
                if (swap) { sv[t] = v2; sv[ixj] = v1; si[t] = i2; si[ixj] = i1; }
            }
            __syncthreads();
        }
    }
    int gi = si[t];
    if (t < K_) {
        g_topidx[b*K_ + t] = gi;
        g_selmap[b*G_ + gi] = t;
    } else {
        g_selmap[b*G_ + gi] = -1;
    }
}

// ---------------- 6. attention per (b, head): 64x64, HD=64 ----------------
__global__ void attn_kernel() {
    int bh = blockIdx.x;
    int b = bh >> 4, h = bh & 15;
    __shared__ float Qs[64][65];
    __shared__ float KV[64][64];
    int t = threadIdx.x;
    const float* qbase = g_q + (b*K_)*D_ + h*HD_;
    const float* kbase = g_k + (b*K_)*D_ + h*HD_;
    const float* vbase = g_v + (b*K_)*D_ + h*HD_;
    for (int i = 0; i < 64; i++) {
        Qs[i][t] = qbase[i*D_ + t];
        KV[i][t] = kbase[i*D_ + t];
    }
    __syncthreads();
    float s[64];
#pragma unroll
    for (int j = 0; j < 64; j++) s[j] = 0.f;
    for (int d = 0; d < 64; d++) {
        float qd = Qs[t][d];
#pragma unroll
        for (int j = 0; j < 64; j++) s[j] += qd * KV[j][d];
    }
    float m = -INFINITY;
#pragma unroll
    for (int j = 0; j < 64; j++) { s[j] *= 0.125f; m = fmaxf(m, s[j]); }
    float sum = 0.f;
#pragma unroll
    for (int j = 0; j < 64; j++) { s[j] = expf(s[j] - m); sum += s[j]; }
    float inv = 1.f / sum;
    __syncthreads();
    for (int i = 0; i < 64; i++) KV[i][t] = vbase[i*D_ + t];
    __syncthreads();
    float* outrow = g_ctx + (b*K_ + t)*D_ + h*HD_;
    for (int d = 0; d < 64; d++) {
        float acc = 0.f;
#pragma unroll
        for (int j = 0; j < 64; j++) acc += s[j] * KV[j][d];
        outrow[d] = acc * inv;
    }
}

// ---------------- 8. scatter-broadcast output ----------------
__global__ void scatter_kernel(float* __restrict__ out) {
    int bg = blockIdx.x;
    int b = bg >> 9, g = bg & 511;
    int k = g_selmap[bg];
    int d4 = threadIdx.x * 4;
    float4 v = make_float4(0.f, 0.f, 0.f, 0.f);
    if (k >= 0) v = *(const float4*)(g_outg + ((b << 6) + k)*D_ + d4);
    float* dst = out + (b*S_ + g*GS_)*D_ + d4;
#pragma unroll
    for (int r = 0; r < GS_; r++) *(float4*)(dst + r*D_) = v;
}

// ---------------- launch ----------------
extern "C" void kernel_launch(void* const* d_in, const int* in_sizes, int n_in,
                              void* d_out, int out_size) {
    const float* hs  = (const float*)d_in[0];
    const float* Wq  = (const float*)d_in[1];
    const float* Wk  = (const float*)d_in[2];
    const float* Wv  = (const float*)d_in[3];
    const float* Wo  = (const float*)d_in[4];
    const float* Ws1 = (const float*)d_in[5];
    const float* bs1 = (const float*)d_in[6];
    const float* Ws2 = (const float*)d_in[7];
    const float* bs2 = (const float*)d_in[8];
    float* out = (float*)d_out;

    float *p_groups, *p_h, *p_q, *p_k, *p_v, *p_ctx, *p_outg;
    cudaGetSymbolAddress((void**)&p_groups, g_groups);
    cudaGetSymbolAddress((void**)&p_h,      g_h);
    cudaGetSymbolAddress((void**)&p_q,      g_q);
    cudaGetSymbolAddress((void**)&p_k,      g_k);
    cudaGetSymbolAddress((void**)&p_v,      g_v);
    cudaGetSymbolAddress((void**)&p_ctx,    g_ctx);
    cudaGetSymbolAddress((void**)&p_outg,   g_outg);

    pool_kernel<<<BG_, 256>>>(hs);
    // scorer hidden: [4096,1024] @ [1024,256]  (N tile 128 -> grid x=2)
    gemm_tf32_3x<false><<<dim3(F_/128, BG_/64, 1), 128>>>(p_groups, Ws1, Ws1, Ws1,
                                                          p_h, p_h, p_h, BG_, F_, D_);
    score_reduce<<<BG_/8, 256>>>(bs1, Ws2, bs2);
    topk_bitonic<<<B_, 512>>>();
    // QKV fused, gather fused via rowmap: [512,1024] @ [1024,1024] x3
    gemm_tf32_3x<true><<<dim3(D_/128, BK_/64, 3), 128>>>(p_groups, Wq, Wk, Wv,
                                                         p_q, p_k, p_v, BK_, D_, D_);
    attn_kernel<<<B_*H_, 64>>>();
    // Wo: [512,1024] @ [1024,1024]
    gemm_tf32_3x<false><<<dim3(D_/128, BK_/64, 1), 128>>>(p_ctx, Wo, Wo, Wo,
                                                          p_outg, p_outg, p_outg, BK_, D_, D_);
    scatter_kernel<<<BG_, 256>>>(out);
}

// round 8
// speedup vs baseline: 1.3909x; 1.3909x over previous
#include <cuda_runtime.h>
#include <math.h>
#include <stdint.h>

// Problem constants
#define B_   8
#define S_   8192
#define D_   1024
#define H_   16
#define GS_  16
#define K_   64
#define HD_  64
#define G_   512            // S/GS groups per batch
#define F_   256            // DH4 scorer hidden
#define BG_  (B_*G_)        // 4096
#define BK_  (B_*K_)        // 512

// ---------------- scratch (static __device__, no allocation) ----------------
__device__ float g_groups[BG_*D_];
__device__ float g_h[BG_*F_];
__device__ float g_scores[BG_];
__device__ int   g_topidx[BK_];
__device__ int   g_selmap[BG_];
__device__ float g_q[BK_*D_];
__device__ float g_k[BK_*D_];
__device__ float g_v[BK_*D_];
__device__ float g_ctx[BK_*D_];
__device__ float g_outg[BK_*D_];

// ---------------- 1. group mean pool ----------------
__global__ void pool_kernel(const float* __restrict__ hs) {
    int bg = blockIdx.x;
    int b = bg >> 9, g = bg & 511;
    const float* base = hs + (b*S_ + g*GS_) * D_;
    int d4 = threadIdx.x * 4;
    float4 acc = make_float4(0.f, 0.f, 0.f, 0.f);
#pragma unroll
    for (int r = 0; r < GS_; r++) {
        float4 v = *(const float4*)(base + r*D_ + d4);
        acc.x += v.x; acc.y += v.y; acc.z += v.z; acc.w += v.w;
    }
    const float inv = 1.0f / (float)GS_;
    acc.x *= inv; acc.y *= inv; acc.z *= inv; acc.w *= inv;
    *(float4*)(g_groups + bg*D_ + d4) = acc;
}

// ---------------- tf32 helpers ----------------
__device__ __forceinline__ uint32_t to_tf32(float x) {
    uint32_t h;
    asm("cvt.rna.tf32.f32 %0, %1;" : "=r"(h) : "f"(x));
    return h;
}

__device__ __forceinline__ void split_tf32(float x, uint32_t& hi, uint32_t& lo) {
    asm("cvt.rna.tf32.f32 %0, %1;" : "=r"(hi) : "f"(x));
    float r = x - __uint_as_float(hi);
    asm("cvt.rna.tf32.f32 %0, %1;" : "=r"(lo) : "f"(r));
}

__device__ __forceinline__ void mma_tf32(float acc[4], const uint32_t a[4], const uint32_t b[2]) {
    asm volatile(
        "mma.sync.aligned.m16n8k8.row.col.f32.tf32.tf32.f32 "
        "{%0,%1,%2,%3}, {%4,%5,%6,%7}, {%8,%9}, {%0,%1,%2,%3};\n"
        : "+f"(acc[0]), "+f"(acc[1]), "+f"(acc[2]), "+f"(acc[3])
        : "r"(a[0]), "r"(a[1]), "r"(a[2]), "r"(a[3]), "r"(b[0]), "r"(b[1]));
}

// ---------------- tensor-core GEMM: C = A[M,K] @ B[K,N] ----------------
// Proven R3 structure: 128 threads (4 warps, 2x2), block tile 64x64, K-chunk 32,
// warp tile 32x32. NSPLIT=3 -> 3xTF32 (fp32-accurate, selection-critical);
// NSPLIT=1 -> plain tf32 (value path, ~1e-4 rel err).
// USE_ROWMAP: A row r reads g_groups[(r>>6)*G_ + g_topidx[r]] (fused gather).
template<bool USE_ROWMAP, int NSPLIT>
__global__ void gemm_tc(const float* __restrict__ A,
                        const float* __restrict__ B0,
                        const float* __restrict__ B1,
                        const float* __restrict__ B2,
                        float* __restrict__ C0,
                        float* __restrict__ C1,
                        float* __restrict__ C2,
                        int M, int N, int Kd) {
    const float* Bm = (blockIdx.z == 0) ? B0 : ((blockIdx.z == 1) ? B1 : B2);
    float* C       = (blockIdx.z == 0) ? C0 : ((blockIdx.z == 1) ? C1 : C2);

    __shared__ float As[64][36];   // [m][k], stride 36 -> conflict-free frag loads
    __shared__ float Bs[32][72];   // [k][n], stride 72 -> conflict-free frag loads

    int tid = threadIdx.x;
    int lane = tid & 31, wid = tid >> 5;
    int wm = wid & 1, wn = wid >> 1;
    int g = lane >> 2, tig = lane & 3;

    int m0 = blockIdx.y * 64, n0 = blockIdx.x * 64;

    // A: thread loads 2 float4 spans (32 floats per row pair of threads)
    int arow = tid >> 1;                 // 0..63
    int acol = (tid & 1) << 4;           // 0 / 16
    int agrow = m0 + arow;
    if (USE_ROWMAP) agrow = ((agrow >> 6) << 9) + g_topidx[agrow];
    const float* Arow = A + (size_t)agrow * Kd;

    int brow = tid >> 2;                 // 0..31
    int bcol = (tid & 3) << 4;           // 0/16/32/48

    float acc[2][4][4];
#pragma unroll
    for (int sm = 0; sm < 2; sm++)
#pragma unroll
        for (int sn = 0; sn < 4; sn++)
#pragma unroll
            for (int i = 0; i < 4; i++) acc[sm][sn][i] = 0.f;

    for (int k0 = 0; k0 < Kd; k0 += 32) {
#pragma unroll
        for (int i = 0; i < 4; i++) {
            float4 v = *(const float4*)(Arow + k0 + acol + i*4);
            *(float4*)(&As[arow][acol + i*4]) = v;
        }
#pragma unroll
        for (int i = 0; i < 4; i++) {
            float4 v = *(const float4*)(Bm + (size_t)(k0 + brow)*N + n0 + bcol + i*4);
            *(float4*)(&Bs[brow][bcol + i*4]) = v;
        }
        __syncthreads();

#pragma unroll
        for (int k8 = 0; k8 < 32; k8 += 8) {
            if (NSPLIT == 3) {
                uint32_t ah[2][4], al[2][4];
#pragma unroll
                for (int sm = 0; sm < 2; sm++) {
                    int mb = wm*32 + sm*16;
                    split_tf32(As[mb + g    ][k8 + tig    ], ah[sm][0], al[sm][0]);
                    split_tf32(As[mb + g + 8][k8 + tig    ], ah[sm][1], al[sm][1]);
                    split_tf32(As[mb + g    ][k8 + tig + 4], ah[sm][2], al[sm][2]);
                    split_tf32(As[mb + g + 8][k8 + tig + 4], ah[sm][3], al[sm][3]);
                }
                uint32_t bh[4][2], bl[4][2];
#pragma unroll
                for (int sn = 0; sn < 4; sn++) {
                    int nb = wn*32 + sn*8 + g;
                    split_tf32(Bs[k8 + tig    ][nb], bh[sn][0], bl[sn][0]);
                    split_tf32(Bs[k8 + tig + 4][nb], bh[sn][1], bl[sn][1]);
                }
#pragma unroll
                for (int sm = 0; sm < 2; sm++)
#pragma unroll
                    for (int sn = 0; sn < 4; sn++) {
                        mma_tf32(acc[sm][sn], al[sm], bh[sn]);
                        mma_tf32(acc[sm][sn], ah[sm], bl[sn]);
                        mma_tf32(acc[sm][sn], ah[sm], bh[sn]);
                    }
            } else {
                uint32_t ah[2][4];
#pragma unroll
                for (int sm = 0; sm < 2; sm++) {
                    int mb = wm*32 + sm*16;
                    ah[sm][0] = to_tf32(As[mb + g    ][k8 + tig    ]);
                    ah[sm][1] = to_tf32(As[mb + g + 8][k8 + tig    ]);
                    ah[sm][2] = to_tf32(As[mb + g    ][k8 + tig + 4]);
                    ah[sm][3] = to_tf32(As[mb + g + 8][k8 + tig + 4]);
                }
                uint32_t bh[4][2];
#pragma unroll
                for (int sn = 0; sn < 4; sn++) {
                    int nb = wn*32 + sn*8 + g;
                    bh[sn][0] = to_tf32(Bs[k8 + tig    ][nb]);
                    bh[sn][1] = to_tf32(Bs[k8 + tig + 4][nb]);
                }
#pragma unroll
                for (int sm = 0; sm < 2; sm++)
#pragma unroll
                    for (int sn = 0; sn < 4; sn++)
                        mma_tf32(acc[sm][sn], ah[sm], bh[sn]);
            }
        }
        __syncthreads();
    }

#pragma unroll
    for (int sm = 0; sm < 2; sm++)
#pragma unroll
        for (int sn = 0; sn < 4; sn++) {
            int row = m0 + wm*32 + sm*16 + g;
            int col = n0 + wn*32 + sn*8 + tig*2;
            *(float2*)(C + (size_t)row*N + col)     = make_float2(acc[sm][sn][0], acc[sm][sn][1]);
            *(float2*)(C + (size_t)(row+8)*N + col) = make_float2(acc[sm][sn][2], acc[sm][sn][3]);
        }
}

// ---------------- 2b. scorer epilogue: bias -> relu -> dot Ws2 ----------------
__global__ void score_reduce(const float* __restrict__ bs1,
                             const float* __restrict__ Ws2,
                             const float* __restrict__ bs2) {
    int g = blockIdx.x * 8 + (threadIdx.x >> 5);
    int lane = threadIdx.x & 31;
    float s = 0.f;
#pragma unroll
    for (int i = 0; i < 8; i++) {
        int f = lane + i*32;
        float v = g_h[g*F_ + f] + bs1[f];
        s += fmaxf(v, 0.f) * Ws2[f];
    }
#pragma unroll
    for (int o = 16; o; o >>= 1) s += __shfl_xor_sync(0xffffffffu, s, o);
    if (lane == 0) g_scores[g] = s + bs2[0];
}

// ---------------- 3. top-64 via bitonic sort (desc by score, asc by idx) -----
__global__ void topk_bitonic() {
    int b = blockIdx.x;
    int t = threadIdx.x;    // 512
    __shared__ float sv[512];
    __shared__ int   si[512];
    sv[t] = g_scores[b*G_ + t];
    si[t] = t;
    __syncthreads();
    for (int k = 2; k <= 512; k <<= 1) {
        for (int j = k >> 1; j > 0; j >>= 1) {
            int ixj = t ^ j;
            if (ixj > t) {
                float v1 = sv[t], v2 = sv[ixj];
                int   i1 = si[t], i2 = si[ixj];
                bool lt12 = (v1 < v2) || (v1 == v2 && i1 > i2);
                bool swap = ((t & k) == 0) ? lt12 : !lt12;
                if (swap) { sv[t] = v2; sv[ixj] = v1; si[t] = i2; si[ixj] = i1; }
            }
            __syncthreads();
        }
    }
    int gi = si[t];
    if (t < K_) {
        g_topidx[b*K_ + t] = gi;
        g_selmap[b*G_ + gi] = t;
    } else {
        g_selmap[b*G_ + gi] = -1;
    }
}

// ---------------- 6. attention per (b, head): 64x64, HD=64 ----------------
__global__ void attn_kernel() {
    int bh = blockIdx.x;
    int b = bh >> 4, h = bh & 15;
    __shared__ float Qs[64][65];
    __shared__ float KV[64][64];
    int t = threadIdx.x;
    const float* qbase = g_q + (b*K_)*D_ + h*HD_;
    const float* kbase = g_k + (b*K_)*D_ + h*HD_;
    const float* vbase = g_v + (b*K_)*D_ + h*HD_;
    for (int i = 0; i < 64; i++) {
        Qs[i][t] = qbase[i*D_ + t];
        KV[i][t] = kbase[i*D_ + t];
    }
    __syncthreads();
    float s[64];
#pragma unroll
    for (int j = 0; j < 64; j++) s[j] = 0.f;
    for (int d = 0; d < 64; d++) {
        float qd = Qs[t][d];
#pragma unroll
        for (int j = 0; j < 64; j++) s[j] += qd * KV[j][d];
    }
    float m = -INFINITY;
#pragma unroll
    for (int j = 0; j < 64; j++) { s[j] *= 0.125f; m = fmaxf(m, s[j]); }
    float sum = 0.f;
#pragma unroll
    for (int j = 0; j < 64; j++) { s[j] = expf(s[j] - m); sum += s[j]; }
    float inv = 1.f / sum;
    __syncthreads();
    for (int i = 0; i < 64; i++) KV[i][t] = vbase[i*D_ + t];
    __syncthreads();
    float* outrow = g_ctx + (b*K_ + t)*D_ + h*HD_;
    for (int d = 0; d < 64; d++) {
        float acc = 0.f;
#pragma unroll
        for (int j = 0; j < 64; j++) acc += s[j] * KV[j][d];
        outrow[d] = acc * inv;
    }
}

// ---------------- 8. scatter-broadcast output ----------------
__global__ void scatter_kernel(float* __restrict__ out) {
    int bg = blockIdx.x;
    int b = bg >> 9, g = bg & 511;
    int k = g_selmap[bg];
    int d4 = threadIdx.x * 4;
    float4 v = make_float4(0.f, 0.f, 0.f, 0.f);
    if (k >= 0) v = *(const float4*)(g_outg + ((b << 6) + k)*D_ + d4);
    float* dst = out + (b*S_ + g*GS_)*D_ + d4;
#pragma unroll
    for (int r = 0; r < GS_; r++) *(float4*)(dst + r*D_) = v;
}

// ---------------- launch ----------------
extern "C" void kernel_launch(void* const* d_in, const int* in_sizes, int n_in,
                              void* d_out, int out_size) {
    const float* hs  = (const float*)d_in[0];
    const float* Wq  = (const float*)d_in[1];
    const float* Wk  = (const float*)d_in[2];
    const float* Wv  = (const float*)d_in[3];
    const float* Wo  = (const float*)d_in[4];
    const float* Ws1 = (const float*)d_in[5];
    const float* bs1 = (const float*)d_in[6];
    const float* Ws2 = (const float*)d_in[7];
    const float* bs2 = (const float*)d_in[8];
    float* out = (float*)d_out;

    float *p_groups, *p_h, *p_q, *p_k, *p_v, *p_ctx, *p_outg;
    cudaGetSymbolAddress((void**)&p_groups, g_groups);
    cudaGetSymbolAddress((void**)&p_h,      g_h);
    cudaGetSymbolAddress((void**)&p_q,      g_q);
    cudaGetSymbolAddress((void**)&p_k,      g_k);
    cudaGetSymbolAddress((void**)&p_v,      g_v);
    cudaGetSymbolAddress((void**)&p_ctx,    g_ctx);
    cudaGetSymbolAddress((void**)&p_outg,   g_outg);

    pool_kernel<<<BG_, 256>>>(hs);
    // scorer hidden (selection-critical, 3xTF32): [4096,1024] @ [1024,256]
    gemm_tc<false,3><<<dim3(F_/64, BG_/64, 1), 128>>>(p_groups, Ws1, Ws1, Ws1,
                                                      p_h, p_h, p_h, BG_, F_, D_);
    score_reduce<<<BG_/8, 256>>>(bs1, Ws2, bs2);
    topk_bitonic<<<B_, 512>>>();
    // QKV fused (value path, 1xTF32), gather fused via rowmap
    gemm_tc<true,1><<<dim3(D_/64, BK_/64, 3), 128>>>(p_groups, Wq, Wk, Wv,
                                                     p_q, p_k, p_v, BK_, D_, D_);
    attn_kernel<<<B_*H_, 64>>>();
    // Wo (value path, 1xTF32): [512,1024] @ [1024,1024]
    gemm_tc<false,1><<<dim3(D_/64, BK_/64, 1), 128>>>(p_ctx, Wo, Wo, Wo,
                                                      p_outg, p_outg, p_outg, BK_, D_, D_);
    scatter_kernel<<<BG_, 256>>>(out);
}

// round 11
// speedup vs baseline: 1.5174x; 1.0909x over previous
#include <cuda_runtime.h>
#include <math.h>
#include <stdint.h>

// Problem constants
#define B_   8
#define S_   8192
#define D_   1024
#define H_   16
#define GS_  16
#define K_   64
#define HD_  64
#define G_   512            // S/GS groups per batch
#define F_   256            // DH4 scorer hidden
#define BG_  (B_*G_)        // 4096
#define BK_  (B_*K_)        // 512

// ---------------- scratch (static __device__, no allocation) ----------------
__device__ float g_groups[BG_*D_];
__device__ float g_h[BG_*F_];
__device__ float g_scores[BG_];
__device__ int   g_topidx[BK_];
__device__ int   g_selmap[BG_];
__device__ float g_q[BK_*D_];
__device__ float g_k[BK_*D_];
__device__ float g_v[BK_*D_];
__device__ float g_ctx[BK_*D_];
__device__ float g_outg[BK_*D_];

// ---------------- 1. group mean pool ----------------
__global__ void pool_kernel(const float* __restrict__ hs) {
    int bg = blockIdx.x;
    int b = bg >> 9, g = bg & 511;
    const float* base = hs + (b*S_ + g*GS_) * D_;
    int d4 = threadIdx.x * 4;
    float4 acc = make_float4(0.f, 0.f, 0.f, 0.f);
#pragma unroll
    for (int r = 0; r < GS_; r++) {
        float4 v = *(const float4*)(base + r*D_ + d4);
        acc.x += v.x; acc.y += v.y; acc.z += v.z; acc.w += v.w;
    }
    const float inv = 1.0f / (float)GS_;
    acc.x *= inv; acc.y *= inv; acc.z *= inv; acc.w *= inv;
    *(float4*)(g_groups + bg*D_ + d4) = acc;
}

// ---------------- tf32 helpers ----------------
__device__ __forceinline__ uint32_t to_tf32(float x) {
    uint32_t h;
    asm("cvt.rna.tf32.f32 %0, %1;" : "=r"(h) : "f"(x));
    return h;
}
__device__ __forceinline__ float to_tf32f(float x) {
    return __uint_as_float(to_tf32(x));
}

__device__ __forceinline__ void split_tf32(float x, uint32_t& hi, uint32_t& lo) {
    asm("cvt.rna.tf32.f32 %0, %1;" : "=r"(hi) : "f"(x));
    float r = x - __uint_as_float(hi);
    asm("cvt.rna.tf32.f32 %0, %1;" : "=r"(lo) : "f"(r));
}

__device__ __forceinline__ void mma_tf32(float acc[4], const uint32_t a[4], const uint32_t b[2]) {
    asm volatile(
        "mma.sync.aligned.m16n8k8.row.col.f32.tf32.tf32.f32 "
        "{%0,%1,%2,%3}, {%4,%5,%6,%7}, {%8,%9}, {%0,%1,%2,%3};\n"
        : "+f"(acc[0]), "+f"(acc[1]), "+f"(acc[2]), "+f"(acc[3])
        : "r"(a[0]), "r"(a[1]), "r"(a[2]), "r"(a[3]), "r"(b[0]), "r"(b[1]));
}

// ---------------- tensor-core GEMM: C = A[M,K] @ B[K,N] ----------------
// 128 threads (4 warps, 2x2), block tile 64x64, K-chunk 32, warp tile 32x32.
// NSPLIT=3 -> 3xTF32 (fp32-accurate, selection-critical), in-loop split.
// NSPLIT=1 -> plain tf32-RNA; conversion done at smem staging -> inner loop is
//             pure LDS+mma. Register prefetch overlaps global loads with mma.
// USE_ROWMAP: A row r reads g_groups[(r>>6)*G_ + g_topidx[r]] (fused gather).
template<bool USE_ROWMAP, int NSPLIT>
__global__ void gemm_tc(const float* __restrict__ A,
                        const float* __restrict__ B0,
                        const float* __restrict__ B1,
                        const float* __restrict__ B2,
                        float* __restrict__ C0,
                        float* __restrict__ C1,
                        float* __restrict__ C2,
                        int M, int N, int Kd) {
    const float* Bm = (blockIdx.z == 0) ? B0 : ((blockIdx.z == 1) ? B1 : B2);
    float* C       = (blockIdx.z == 0) ? C0 : ((blockIdx.z == 1) ? C1 : C2);

    __shared__ float As[64][36];   // [m][k], stride 36 -> conflict-free frag loads
    __shared__ float Bs[32][72];   // [k][n], stride 72 -> conflict-free frag loads

    int tid = threadIdx.x;
    int lane = tid & 31, wid = tid >> 5;
    int wm = wid & 1, wn = wid >> 1;
    int g = lane >> 2, tig = lane & 3;

    int m0 = blockIdx.y * 64, n0 = blockIdx.x * 64;

    int arow = tid >> 1;                 // 0..63
    int acol = (tid & 1) << 4;           // 0 / 16
    int agrow = m0 + arow;
    if (USE_ROWMAP) agrow = ((agrow >> 6) << 9) + g_topidx[agrow];
    const float* Arow = A + (size_t)agrow * Kd;

    int brow = tid >> 2;                 // 0..31
    int bcol = (tid & 3) << 4;           // 0/16/32/48
    // Brow points at B[brow][n0+bcol]; chunk k0 adds k0*N (rows advance with k)
    const float* Brow = Bm + (size_t)brow * N + n0 + bcol;

    float acc[2][4][4];
#pragma unroll
    for (int sm = 0; sm < 2; sm++)
#pragma unroll
        for (int sn = 0; sn < 4; sn++)
#pragma unroll
            for (int i = 0; i < 4; i++) acc[sm][sn][i] = 0.f;

    // prologue: prefetch chunk 0 into registers
    // pa[i]: A[agrow][acol + 4i .. acol + 4i+3]
    // pb[i]: B[brow][n0 + bcol + 4i .. +3]   (same row, 16-col span — matches store)
    float4 pa[4], pb[4];
#pragma unroll
    for (int i = 0; i < 4; i++) {
        pa[i] = *(const float4*)(Arow + acol + i*4);
        pb[i] = *(const float4*)(Brow + i*4);
    }

    for (int k0 = 0; k0 < Kd; k0 += 32) {
        // ---- stage prefetched tiles into smem (convert for NSPLIT==1) ----
#pragma unroll
        for (int i = 0; i < 4; i++) {
            float4 v = pa[i];
            if (NSPLIT == 1) {
                v.x = to_tf32f(v.x); v.y = to_tf32f(v.y);
                v.z = to_tf32f(v.z); v.w = to_tf32f(v.w);
            }
            *(float4*)(&As[arow][acol + i*4]) = v;
        }
#pragma unroll
        for (int i = 0; i < 4; i++) {
            float4 v = pb[i];
            if (NSPLIT == 1) {
                v.x = to_tf32f(v.x); v.y = to_tf32f(v.y);
                v.z = to_tf32f(v.z); v.w = to_tf32f(v.w);
            }
            *(float4*)(&Bs[brow][bcol + i*4]) = v;
        }
        __syncthreads();

        // ---- prefetch next chunk (overlaps with mma below) ----
        if (k0 + 32 < Kd) {
#pragma unroll
            for (int i = 0; i < 4; i++) {
                pa[i] = *(const float4*)(Arow + k0 + 32 + acol + i*4);
                pb[i] = *(const float4*)(Brow + (size_t)(k0 + 32) * N + i*4);
            }
        }

        // ---- mma over the chunk ----
#pragma unroll
        for (int k8 = 0; k8 < 32; k8 += 8) {
            if (NSPLIT == 3) {
                uint32_t ah[2][4], al[2][4];
#pragma unroll
                for (int sm = 0; sm < 2; sm++) {
                    int mb = wm*32 + sm*16;
                    split_tf32(As[mb + g    ][k8 + tig    ], ah[sm][0], al[sm][0]);
                    split_tf32(As[mb + g + 8][k8 + tig    ], ah[sm][1], al[sm][1]);
                    split_tf32(As[mb + g    ][k8 + tig + 4], ah[sm][2], al[sm][2]);
                    split_tf32(As[mb + g + 8][k8 + tig + 4], ah[sm][3], al[sm][3]);
                }
                uint32_t bh[4][2], bl[4][2];
#pragma unroll
                for (int sn = 0; sn < 4; sn++) {
                    int nb = wn*32 + sn*8 + g;
                    split_tf32(Bs[k8 + tig    ][nb], bh[sn][0], bl[sn][0]);
                    split_tf32(Bs[k8 + tig + 4][nb], bh[sn][1], bl[sn][1]);
                }
#pragma unroll
                for (int sm = 0; sm < 2; sm++)
#pragma unroll
                    for (int sn = 0; sn < 4; sn++) {
                        mma_tf32(acc[sm][sn], al[sm], bh[sn]);
                        mma_tf32(acc[sm][sn], ah[sm], bl[sn]);
                        mma_tf32(acc[sm][sn], ah[sm], bh[sn]);
                    }
            } else {
                uint32_t ah[2][4];
#pragma unroll
                for (int sm = 0; sm < 2; sm++) {
                    int mb = wm*32 + sm*16;
                    ah[sm][0] = __float_as_uint(As[mb + g    ][k8 + tig    ]);
                    ah[sm][1] = __float_as_uint(As[mb + g + 8][k8 + tig    ]);
                    ah[sm][2] = __float_as_uint(As[mb + g    ][k8 + tig + 4]);
                    ah[sm][3] = __float_as_uint(As[mb + g + 8][k8 + tig + 4]);
                }
                uint32_t bh[4][2];
#pragma unroll
                for (int sn = 0; sn < 4; sn++) {
                    int nb = wn*32 + sn*8 + g;
                    bh[sn][0] = __float_as_uint(Bs[k8 + tig    ][nb]);
                    bh[sn][1] = __float_as_uint(Bs[k8 + tig + 4][nb]);
                }
#pragma unroll
                for (int sm = 0; sm < 2; sm++)
#pragma unroll
                    for (int sn = 0; sn < 4; sn++)
                        mma_tf32(acc[sm][sn], ah[sm], bh[sn]);
            }
        }
        __syncthreads();
    }

#pragma unroll
    for (int sm = 0; sm < 2; sm++)
#pragma unroll
        for (int sn = 0; sn < 4; sn++) {
            int row = m0 + wm*32 + sm*16 + g;
            int col = n0 + wn*32 + sn*8 + tig*2;
            *(float2*)(C + (size_t)row*N + col)     = make_float2(acc[sm][sn][0], acc[sm][sn][1]);
            *(float2*)(C + (size_t)(row+8)*N + col) = make_float2(acc[sm][sn][2], acc[sm][sn][3]);
        }
}

// ---------------- 2b. scorer epilogue: bias -> relu -> dot Ws2 ----------------
__global__ void score_reduce(const float* __restrict__ bs1,
                             const float* __restrict__ Ws2,
                             const float* __restrict__ bs2) {
    int g = blockIdx.x * 8 + (threadIdx.x >> 5);
    int lane = threadIdx.x & 31;
    float s = 0.f;
#pragma unroll
    for (int i = 0; i < 8; i++) {
        int f = lane + i*32;
        float v = g_h[g*F_ + f] + bs1[f];
        s += fmaxf(v, 0.f) * Ws2[f];
    }
#pragma unroll
    for (int o = 16; o; o >>= 1) s += __shfl_xor_sync(0xffffffffu, s, o);
    if (lane == 0) g_scores[g] = s + bs2[0];
}

// ---------------- 3. top-64 via bitonic sort (desc by score, asc by idx) -----
__global__ void topk_bitonic() {
    int b = blockIdx.x;
    int t = threadIdx.x;    // 512
    __shared__ float sv[512];
    __shared__ int   si[512];
    sv[t] = g_scores[b*G_ + t];
    si[t] = t;
    __syncthreads();
    for (int k = 2; k <= 512; k <<= 1) {
        for (int j = k >> 1; j > 0; j >>= 1) {
            int ixj = t ^ j;
            if (ixj > t) {
                float v1 = sv[t], v2 = sv[ixj];
                int   i1 = si[t], i2 = si[ixj];
                bool lt12 = (v1 < v2) || (v1 == v2 && i1 > i2);
                bool swap = ((t & k) == 0) ? lt12 : !lt12;
                if (swap) { sv[t] = v2; sv[ixj] = v1; si[t] = i2; si[ixj] = i1; }
            }
            __syncthreads();
        }
    }
    int gi = si[t];
    if (t < K_) {
        g_topidx[b*K_ + t] = gi;
        g_selmap[b*G_ + gi] = t;
    } else {
        g_selmap[b*G_ + gi] = -1;
    }
}

// ---------------- 6. attention per (b, head): 64x64, HD=64 ----------------
__global__ void attn_kernel() {
    int bh = blockIdx.x;
    int b = bh >> 4, h = bh & 15;
    __shared__ float Qs[64][65];
    __shared__ float KV[64][64];
    int t = threadIdx.x;
    const float* qbase = g_q + (b*K_)*D_ + h*HD_;
    const float* kbase = g_k + (b*K_)*D_ + h*HD_;
    const float* vbase = g_v + (b*K_)*D_ + h*HD_;
    for (int i = 0; i < 64; i++) {
        Qs[i][t] = qbase[i*D_ + t];
        KV[i][t] = kbase[i*D_ + t];
    }
    __syncthreads();
    float s[64];
#pragma unroll
    for (int j = 0; j < 64; j++) s[j] = 0.f;
    for (int d = 0; d < 64; d++) {
        float qd = Qs[t][d];
#pragma unroll
        for (int j = 0; j < 64; j++) s[j] += qd * KV[j][d];
    }
    float m = -INFINITY;
#pragma unroll
    for (int j = 0; j < 64; j++) { s[j] *= 0.125f; m = fmaxf(m, s[j]); }
    float sum = 0.f;
#pragma unroll
    for (int j = 0; j < 64; j++) { s[j] = expf(s[j] - m); sum += s[j]; }
    float inv = 1.f / sum;
    __syncthreads();
    for (int i = 0; i < 64; i++) KV[i][t] = vbase[i*D_ + t];
    __syncthreads();
    float* outrow = g_ctx + (b*K_ + t)*D_ + h*HD_;
    for (int d = 0; d < 64; d++) {
        float acc = 0.f;
#pragma unroll
        for (int j = 0; j < 64; j++) acc += s[j] * KV[j][d];
        outrow[d] = acc * inv;
    }
}

// ---------------- 8. scatter-broadcast output ----------------
__global__ void scatter_kernel(float* __restrict__ out) {
    int bg = blockIdx.x;
    int b = bg >> 9, g = bg & 511;
    int k = g_selmap[bg];
    int d4 = threadIdx.x * 4;
    float4 v = make_float4(0.f, 0.f, 0.f, 0.f);
    if (k >= 0) v = *(const float4*)(g_outg + ((b << 6) + k)*D_ + d4);
    float* dst = out + (b*S_ + g*GS_)*D_ + d4;
#pragma unroll
    for (int r = 0; r < GS_; r++) *(float4*)(dst + r*D_) = v;
}

// ---------------- launch ----------------
extern "C" void kernel_launch(void* const* d_in, const int* in_sizes, int n_in,
                              void* d_out, int out_size) {
    const float* hs  = (const float*)d_in[0];
    const float* Wq  = (const float*)d_in[1];
    const float* Wk  = (const float*)d_in[2];
    const float* Wv  = (const float*)d_in[3];
    const float* Wo  = (const float*)d_in[4];
    const float* Ws1 = (const float*)d_in[5];
    const float* bs1 = (const float*)d_in[6];
    const float* Ws2 = (const float*)d_in[7];
    const float* bs2 = (const float*)d_in[8];
    float* out = (float*)d_out;

    float *p_groups, *p_h, *p_q, *p_k, *p_v, *p_ctx, *p_outg;
    cudaGetSymbolAddress((void**)&p_groups, g_groups);
    cudaGetSymbolAddress((void**)&p_h,      g_h);
    cudaGetSymbolAddress((void**)&p_q,      g_q);
    cudaGetSymbolAddress((void**)&p_k,      g_k);
    cudaGetSymbolAddress((void**)&p_v,      g_v);
    cudaGetSymbolAddress((void**)&p_ctx,    g_ctx);
    cudaGetSymbolAddress((void**)&p_outg,   g_outg);

    pool_kernel<<<BG_, 256>>>(hs);
    // scorer hidden (selection-critical, 3xTF32): [4096,1024] @ [1024,256]
    gemm_tc<false,3><<<dim3(F_/64, BG_/64, 1), 128>>>(p_groups, Ws1, Ws1, Ws1,
                                                      p_h, p_h, p_h, BG_, F_, D_);
    score_reduce<<<BG_/8, 256>>>(bs1, Ws2, bs2);
    topk_bitonic<<<B_, 512>>>();
    // QKV fused (value path, 1xTF32 staged-convert), gather fused via rowmap
    gemm_tc<true,1><<<dim3(D_/64, BK_/64, 3), 128>>>(p_groups, Wq, Wk, Wv,
                                                     p_q, p_k, p_v, BK_, D_, D_);
    attn_kernel<<<B_*H_, 64>>>();
    // Wo (value path, 1xTF32): [512,1024] @ [1024,1024]
    gemm_tc<false,1><<<dim3(D_/64, BK_/64, 1), 128>>>(p_ctx, Wo, Wo, Wo,
                                                      p_outg, p_outg, p_outg, BK_, D_, D_);
    scatter_kernel<<<BG_, 256>>>(out);
}